// round 9
// baseline (speedup 1.0000x reference)
#include <cuda_runtime.h>
#include <cuda_bf16.h>
#include <cstdint>

// Problem constants
#define BB 2
#define TT 4096
#define EE 768
#define HH 12
#define SS 64
#define WW 256
#define CC 16
#define NN (BB * TT)   // 8192

// ---------------------------------------------------------------------------
// Planar split-bf16 scratch: hi plane = bf16(x), lo plane = bf16(x - hi)
// ---------------------------------------------------------------------------
__device__ __nv_bfloat16 g_xh[(size_t)NN * EE], g_xl[(size_t)NN * EE];
__device__ __nv_bfloat16 g_wh[(size_t)3 * EE * EE], g_wl[(size_t)3 * EE * EE];
__device__ __nv_bfloat16 g_qh[(size_t)BB * HH * TT * SS], g_ql[(size_t)BB * HH * TT * SS];
__device__ __nv_bfloat16 g_kh[(size_t)BB * HH * TT * SS], g_kl[(size_t)BB * HH * TT * SS];
__device__ __nv_bfloat16 g_vh[(size_t)BB * HH * TT * SS], g_vl[(size_t)BB * HH * TT * SS];

// ---------------------------------------------------------------------------
// Helpers
// ---------------------------------------------------------------------------
__device__ __forceinline__ unsigned pack2bf(float lo_elem, float hi_elem) {
    unsigned r;
    asm("cvt.rn.bf16x2.f32 %0, %1, %2;" : "=r"(r) : "f"(hi_elem), "f"(lo_elem));
    return r;
}
__device__ __forceinline__ unsigned smaddr(const void* p) {
    return (unsigned)__cvta_generic_to_shared(p);
}
__device__ __forceinline__ void cp16(unsigned dst, const void* src) {
    asm volatile("cp.async.cg.shared.global [%0], [%1], 16;" :: "r"(dst), "l"(src));
}
#define CP_COMMIT asm volatile("cp.async.commit_group;")
#define CP_WAIT0  asm volatile("cp.async.wait_group 0;")
#define CP_WAIT1  asm volatile("cp.async.wait_group 1;")
__device__ __forceinline__ void ldm_x4(unsigned a, unsigned& r0, unsigned& r1,
                                       unsigned& r2, unsigned& r3) {
    asm volatile("ldmatrix.sync.aligned.m8n8.x4.shared.b16 {%0,%1,%2,%3},[%4];"
                 : "=r"(r0), "=r"(r1), "=r"(r2), "=r"(r3) : "r"(a));
}
__device__ __forceinline__ void ldm_x4t(unsigned a, unsigned& r0, unsigned& r1,
                                        unsigned& r2, unsigned& r3) {
    asm volatile("ldmatrix.sync.aligned.m8n8.x4.trans.shared.b16 {%0,%1,%2,%3},[%4];"
                 : "=r"(r0), "=r"(r1), "=r"(r2), "=r"(r3) : "r"(a));
}
__device__ __forceinline__ void mma_bf16(float* d, const unsigned* a,
                                         unsigned b0, unsigned b1) {
    asm volatile(
        "mma.sync.aligned.m16n8k16.row.col.f32.bf16.bf16.f32 "
        "{%0,%1,%2,%3},{%4,%5,%6,%7},{%8,%9},{%0,%1,%2,%3};"
        : "+f"(d[0]), "+f"(d[1]), "+f"(d[2]), "+f"(d[3])
        : "r"(a[0]), "r"(a[1]), "r"(a[2]), "r"(a[3]), "r"(b0), "r"(b1));
}

// ---------------------------------------------------------------------------
// Pass 0: fp32 -> planar split bf16 (one launch for x, wq, wk, wv)
// ---------------------------------------------------------------------------
#define NX4 (NN * EE / 4)
#define NW4 (EE * EE / 4)
#define NTOT4 (NX4 + 3 * NW4)

__global__ __launch_bounds__(256) void convert_kernel(
    const float* __restrict__ x,  const float* __restrict__ wq,
    const float* __restrict__ wk, const float* __restrict__ wv)
{
    int i = blockIdx.x * 256 + threadIdx.x;
    if (i >= NTOT4) return;
    const float4* src;
    __nv_bfloat16 *dh, *dl;
    int j;
    if (i < NX4)                { src = (const float4*)x;  dh = g_xh;              dl = g_xl;              j = i; }
    else if (i < NX4 + NW4)     { src = (const float4*)wq; dh = g_wh;              dl = g_wl;              j = i - NX4; }
    else if (i < NX4 + 2 * NW4) { src = (const float4*)wk; dh = g_wh + EE * EE;     dl = g_wl + EE * EE;     j = i - NX4 - NW4; }
    else                        { src = (const float4*)wv; dh = g_wh + 2 * EE * EE; dl = g_wl + 2 * EE * EE; j = i - NX4 - 2 * NW4; }
    float4 v = src[j];
    float hx = __bfloat162float(__float2bfloat16(v.x));
    float hy = __bfloat162float(__float2bfloat16(v.y));
    float hz = __bfloat162float(__float2bfloat16(v.z));
    float hw = __bfloat162float(__float2bfloat16(v.w));
    uint2 ho, lo;
    ho.x = pack2bf(v.x, v.y);           ho.y = pack2bf(v.z, v.w);
    lo.x = pack2bf(v.x - hx, v.y - hy); lo.y = pack2bf(v.z - hz, v.w - hw);
    ((uint2*)dh)[j] = ho;
    ((uint2*)dl)[j] = lo;
}

// ---------------------------------------------------------------------------
// Pass 1: Q/K/V GEMM via mma.sync, round-5 structure (24KB static smem,
// register prefetch, k-step 16) with planar input/output (no byte_perm).
// 128x128 tile, 256 threads = 8 warps (2x4), warp tile 64x32, 3-term split.
// ---------------------------------------------------------------------------
#define QST 24   // smem row stride (bf16 elems) for 16-wide k tiles

__global__ __launch_bounds__(256) void qkv_mma_kernel()
{
    __shared__ __nv_bfloat16 Ah[128 * QST], Al[128 * QST];
    __shared__ __nv_bfloat16 Bh[128 * QST], Bl[128 * QST];

    const int which = blockIdx.z;
    const __nv_bfloat16* wph = g_wh + (size_t)which * EE * EE;
    const __nv_bfloat16* wpl = g_wl + (size_t)which * EE * EE;
    __nv_bfloat16* dsth = (which == 0) ? g_qh : (which == 1) ? g_kh : g_vh;
    __nv_bfloat16* dstl = (which == 0) ? g_ql : (which == 1) ? g_kl : g_vl;
    const float scale = (which == 0) ? 0.125f : 1.0f;

    const int rowBase = blockIdx.x * 128;
    const int colBase = blockIdx.y * 128;
    const int t    = threadIdx.x;
    const int lane = t & 31;
    const int w    = t >> 5;
    const int wm   = (w >> 2) * 64;
    const int wn   = (w & 3) * 32;

    // granule mapping: 128 rows x 2 granules (8 bf16 each) per plane
    const int grow = t >> 1;
    const int gcol = (t & 1) * 8;

    float acc[4][4][4];
    #pragma unroll
    for (int mt = 0; mt < 4; mt++)
        #pragma unroll
        for (int nt = 0; nt < 4; nt++)
            #pragma unroll
            for (int e = 0; e < 4; e++) acc[mt][nt][e] = 0.0f;

    uint4 vah, val, vbh, vbl;
    // prologue load (k0 = 0)
    vah = *(const uint4*)&g_xh[(size_t)(rowBase + grow) * EE + gcol];
    val = *(const uint4*)&g_xl[(size_t)(rowBase + grow) * EE + gcol];
    vbh = *(const uint4*)&wph [(size_t)(colBase + grow) * EE + gcol];
    vbl = *(const uint4*)&wpl [(size_t)(colBase + grow) * EE + gcol];

    for (int k0 = 0; k0 < EE; k0 += 16) {
        __syncthreads();
        *(uint4*)&Ah[grow * QST + gcol] = vah;
        *(uint4*)&Al[grow * QST + gcol] = val;
        *(uint4*)&Bh[grow * QST + gcol] = vbh;
        *(uint4*)&Bl[grow * QST + gcol] = vbl;
        __syncthreads();

        if (k0 + 16 < EE) {
            vah = *(const uint4*)&g_xh[(size_t)(rowBase + grow) * EE + k0 + 16 + gcol];
            val = *(const uint4*)&g_xl[(size_t)(rowBase + grow) * EE + k0 + 16 + gcol];
            vbh = *(const uint4*)&wph [(size_t)(colBase + grow) * EE + k0 + 16 + gcol];
            vbl = *(const uint4*)&wpl [(size_t)(colBase + grow) * EE + k0 + 16 + gcol];
        }

        unsigned ah[4][4], al[4][4], bh[2][4], bl[2][4];
        #pragma unroll
        for (int mt = 0; mt < 4; mt++) {
            const int off = (wm + mt * 16 + (lane & 15)) * QST + ((lane >> 4) << 3);
            ldm_x4(smaddr(&Ah[off]), ah[mt][0], ah[mt][1], ah[mt][2], ah[mt][3]);
            ldm_x4(smaddr(&Al[off]), al[mt][0], al[mt][1], al[mt][2], al[mt][3]);
        }
        #pragma unroll
        for (int g = 0; g < 2; g++) {
            const int off = (wn + g * 16 + ((lane >> 4) << 3) + (lane & 7)) * QST
                          + (((lane >> 3) & 1) << 3);
            ldm_x4(smaddr(&Bh[off]), bh[g][0], bh[g][1], bh[g][2], bh[g][3]);
            ldm_x4(smaddr(&Bl[off]), bl[g][0], bl[g][1], bl[g][2], bl[g][3]);
        }
        #pragma unroll
        for (int mt = 0; mt < 4; mt++)
            #pragma unroll
            for (int nt = 0; nt < 4; nt++) {
                const int g  = nt >> 1;
                const int hb = (nt & 1) * 2;
                mma_bf16(acc[mt][nt], ah[mt], bh[g][hb], bh[g][hb + 1]);
                mma_bf16(acc[mt][nt], al[mt], bh[g][hb], bh[g][hb + 1]);
                mma_bf16(acc[mt][nt], ah[mt], bl[g][hb], bl[g][hb + 1]);
            }
    }

    // epilogue: planar split store [b][h][t][d]
    #pragma unroll
    for (int mt = 0; mt < 4; mt++) {
        const int rg0 = rowBase + wm + mt * 16 + (lane >> 2);
        #pragma unroll
        for (int nt = 0; nt < 4; nt++) {
            const int jc = colBase + wn + nt * 8 + (lane & 3) * 2;
            const int h  = jc >> 6;
            const int d  = jc & 63;
            #pragma unroll
            for (int rh = 0; rh < 2; rh++) {
                const int rg = rg0 + rh * 8;
                const int bb = rg >> 12;
                const int tt = rg & (TT - 1);
                const size_t idx = (((size_t)(bb * HH + h) * TT) + tt) * SS + d;
                const float v0 = acc[mt][nt][rh * 2 + 0] * scale;
                const float v1 = acc[mt][nt][rh * 2 + 1] * scale;
                const float h0 = __bfloat162float(__float2bfloat16(v0));
                const float h1 = __bfloat162float(__float2bfloat16(v1));
                *(unsigned*)&dsth[idx] = pack2bf(v0, v1);
                *(unsigned*)&dstl[idx] = pack2bf(v0 - h0, v1 - h1);
            }
        }
    }
}

// ---------------------------------------------------------------------------
// Pass 2: fused flash attention. Separate K pair + V pair smem buffers
// (73.7KB total -> 2 CTAs/SM). Phase-overlapped cp.async: V(t) loads behind
// QK(t); K(t+1) loads behind softmax+PV(t). Boundary chunks analytic.
// ---------------------------------------------------------------------------
#define AP_ST    144
#define AP_PLANE (128 * AP_ST)          // 18432 B
#define ATT_SMEM (4 * AP_PLANE)         // Kh Kl Vh Vl = 73728 B

__global__ __launch_bounds__(256) void attn_mma_kernel(float* __restrict__ out)
{
    extern __shared__ char smraw[];
    const unsigned su = smaddr(smraw);
    const unsigned pKh = su, pKl = su + AP_PLANE;
    const unsigned pVh = su + 2 * AP_PLANE, pVl = su + 3 * AP_PLANE;

    const int c    = blockIdx.x >> 1;
    const int half = blockIdx.x & 1;
    const int bh   = blockIdx.y;
    const int b = bh / HH;
    const int h = bh % HH;

    const int t    = threadIdx.x;
    const int lane = t & 31;
    const int w    = t >> 5;

    // ---- stage Q planes into K buffers, build Q frags ----
    {
        const size_t qoff = ((size_t)bh * TT + c * WW + half * 128) * SS;
        #pragma unroll
        for (int j = 0; j < 4; j++) {
            const int gi  = t + j * 256;
            const int row = gi >> 3;
            const int gc  = gi & 7;
            const unsigned d = row * AP_ST + gc * 16;
            const size_t s = qoff + (size_t)row * SS + gc * 8;
            cp16(pKh + d, g_qh + s);
            cp16(pKl + d, g_ql + s);
        }
        CP_COMMIT; CP_WAIT0;
    }
    __syncthreads();

    unsigned qh[4][4], ql[4][4];
    #pragma unroll
    for (int kt = 0; kt < 4; kt++) {
        const unsigned off = (w * 16 + (lane & 15)) * AP_ST
                           + (kt * 16 + ((lane >> 4) << 3)) * 2;
        ldm_x4(pKh + off, qh[kt][0], qh[kt][1], qh[kt][2], qh[kt][3]);
        ldm_x4(pKl + off, ql[kt][0], ql[kt][1], ql[kt][2], ql[kt][3]);
    }
    __syncthreads();   // all Q-frag reads done before K tile overwrites

    float m0 = -1e30f, m1 = -1e30f, l0 = 0.0f, l1 = 0.0f;
    float o_fr[8][4];
    #pragma unroll
    for (int nd = 0; nd < 8; nd++)
        #pragma unroll
        for (int e = 0; e < 4; e++) o_fr[nd][e] = 0.0f;

    const int r0 = half * 128 + w * 16 + (lane >> 2);
    const int r1 = r0 + 8;

    // ---- analytic boundary-chunk contribution ----
    if (c == 0) {
        if (r0 > 0) { m0 = 0.0f; l0 = (float)r0; }
        if (r1 > 0) { m1 = 0.0f; l1 = (float)r1; }
    } else if (c == CC - 1) {
        const int a0 = 255 - r0, a1 = 255 - r1;
        if (a0 > 0) { m0 = 0.0f; l0 = (float)a0; }
        if (a1 > 0) { m1 = 0.0f; l1 = (float)a1; }
    }

    const int tstart = (c == 0) ? 2 : 0;
    const int tend   = (c == CC - 1) ? 4 : 6;

    #define ISSUE_K(NT)                                                         \
    {                                                                           \
        const int kc_ = c - 1 + ((NT) >> 1);                                    \
        const size_t koff = ((size_t)bh * TT + kc_ * WW + ((NT) & 1) * 128) * SS; \
        _Pragma("unroll")                                                       \
        for (int j = 0; j < 4; j++) {                                           \
            const int gi  = t + j * 256;                                        \
            const int row = gi >> 3;                                            \
            const int gc  = gi & 7;                                             \
            const unsigned d = row * AP_ST + gc * 16;                           \
            const size_t s = koff + (size_t)row * SS + gc * 8;                  \
            cp16(pKh + d, g_kh + s);                                            \
            cp16(pKl + d, g_kl + s);                                            \
        }                                                                       \
    }
    #define ISSUE_V(NT)                                                         \
    {                                                                           \
        const int kc_ = c - 1 + ((NT) >> 1);                                    \
        const size_t koff = ((size_t)bh * TT + kc_ * WW + ((NT) & 1) * 128) * SS; \
        _Pragma("unroll")                                                       \
        for (int j = 0; j < 4; j++) {                                           \
            const int gi  = t + j * 256;                                        \
            const int row = gi >> 3;                                            \
            const int gc  = gi & 7;                                             \
            const unsigned d = row * AP_ST + gc * 16;                           \
            const size_t s = koff + (size_t)row * SS + gc * 8;                  \
            cp16(pVh + d, g_vh + s);                                            \
            cp16(pVl + d, g_vl + s);                                            \
        }                                                                       \
    }

    ISSUE_K(tstart); CP_COMMIT;

    for (int nt = tstart; nt < tend; nt++) {
        // V buffer free (PV of prev tile done via trailing barrier)
        ISSUE_V(nt); CP_COMMIT;
        CP_WAIT1;                   // K(nt) complete (V may still be in flight)
        __syncthreads();

        // ---- QK from K planes ----
        float s_fr[16][4];
        #pragma unroll
        for (int n = 0; n < 16; n++)
            #pragma unroll
            for (int e = 0; e < 4; e++) s_fr[n][e] = 0.0f;

        #pragma unroll
        for (int kt = 0; kt < 4; kt++) {
            #pragma unroll
            for (int g = 0; g < 8; g++) {
                unsigned kbf[4], klf[4];
                const unsigned off = (g * 16 + ((lane >> 4) << 3) + (lane & 7)) * AP_ST
                                   + (kt * 16 + (((lane >> 3) & 1) << 3)) * 2;
                ldm_x4(pKh + off, kbf[0], kbf[1], kbf[2], kbf[3]);
                ldm_x4(pKl + off, klf[0], klf[1], klf[2], klf[3]);
                #pragma unroll
                for (int h2 = 0; h2 < 2; h2++) {
                    const int n = g * 2 + h2;
                    mma_bf16(s_fr[n], qh[kt], kbf[h2 * 2], kbf[h2 * 2 + 1]);
                    mma_bf16(s_fr[n], ql[kt], kbf[h2 * 2], kbf[h2 * 2 + 1]);
                    mma_bf16(s_fr[n], qh[kt], klf[h2 * 2], klf[h2 * 2 + 1]);
                }
            }
        }
        __syncthreads();            // all warps done reading K planes
        if (nt + 1 < tend) { ISSUE_K(nt + 1); CP_COMMIT; }

        // ---- online softmax (overlaps K(nt+1) load) ----
        float rm0 = -1e30f, rm1 = -1e30f;
        #pragma unroll
        for (int n = 0; n < 16; n++) {
            rm0 = fmaxf(rm0, fmaxf(s_fr[n][0], s_fr[n][1]));
            rm1 = fmaxf(rm1, fmaxf(s_fr[n][2], s_fr[n][3]));
        }
        #pragma unroll
        for (int off = 1; off <= 2; off <<= 1) {
            rm0 = fmaxf(rm0, __shfl_xor_sync(0xFFFFFFFFu, rm0, off));
            rm1 = fmaxf(rm1, __shfl_xor_sync(0xFFFFFFFFu, rm1, off));
        }
        const float mn0 = fmaxf(m0, rm0);
        const float mn1 = fmaxf(m1, rm1);
        const float al0 = __expf(m0 - mn0);
        const float al1 = __expf(m1 - mn1);
        float rs0 = 0.0f, rs1 = 0.0f;
        #pragma unroll
        for (int n = 0; n < 16; n++) {
            s_fr[n][0] = __expf(s_fr[n][0] - mn0);
            s_fr[n][1] = __expf(s_fr[n][1] - mn0);
            s_fr[n][2] = __expf(s_fr[n][2] - mn1);
            s_fr[n][3] = __expf(s_fr[n][3] - mn1);
            rs0 += s_fr[n][0] + s_fr[n][1];
            rs1 += s_fr[n][2] + s_fr[n][3];
        }
        #pragma unroll
        for (int off = 1; off <= 2; off <<= 1) {
            rs0 += __shfl_xor_sync(0xFFFFFFFFu, rs0, off);
            rs1 += __shfl_xor_sync(0xFFFFFFFFu, rs1, off);
        }
        l0 = l0 * al0 + rs0;  m0 = mn0;
        l1 = l1 * al1 + rs1;  m1 = mn1;
        #pragma unroll
        for (int nd = 0; nd < 8; nd++) {
            o_fr[nd][0] *= al0; o_fr[nd][1] *= al0;
            o_fr[nd][2] *= al1; o_fr[nd][3] *= al1;
        }

        // ---- wait V(nt), then PV (overlaps K(nt+1) load) ----
        if (nt + 1 < tend) { CP_WAIT1; } else { CP_WAIT0; }
        __syncthreads();

        #pragma unroll
        for (int ktj = 0; ktj < 8; ktj++) {
            const float* pe = s_fr[2 * ktj];
            const float* po = s_fr[2 * ktj + 1];
            const float heA = __bfloat162float(__float2bfloat16(pe[0]));
            const float heB = __bfloat162float(__float2bfloat16(pe[1]));
            const float heC = __bfloat162float(__float2bfloat16(pe[2]));
            const float heD = __bfloat162float(__float2bfloat16(pe[3]));
            const float hoA = __bfloat162float(__float2bfloat16(po[0]));
            const float hoB = __bfloat162float(__float2bfloat16(po[1]));
            const float hoC = __bfloat162float(__float2bfloat16(po[2]));
            const float hoD = __bfloat162float(__float2bfloat16(po[3]));
            unsigned pah[4], pal[4];
            pah[0] = pack2bf(pe[0], pe[1]);
            pah[1] = pack2bf(pe[2], pe[3]);
            pah[2] = pack2bf(po[0], po[1]);
            pah[3] = pack2bf(po[2], po[3]);
            pal[0] = pack2bf(pe[0] - heA, pe[1] - heB);
            pal[1] = pack2bf(pe[2] - heC, pe[3] - heD);
            pal[2] = pack2bf(po[0] - hoA, po[1] - hoB);
            pal[3] = pack2bf(po[2] - hoC, po[3] - hoD);

            #pragma unroll
            for (int g = 0; g < 4; g++) {
                unsigned vbf[4], vlf[4];
                const unsigned off = (ktj * 16 + (lane & 15)) * AP_ST
                                   + (g * 16 + ((lane >> 4) << 3)) * 2;
                ldm_x4t(pVh + off, vbf[0], vbf[1], vbf[2], vbf[3]);
                ldm_x4t(pVl + off, vlf[0], vlf[1], vlf[2], vlf[3]);
                #pragma unroll
                for (int h2 = 0; h2 < 2; h2++) {
                    const int nd = g * 2 + h2;
                    mma_bf16(o_fr[nd], pah, vbf[h2 * 2], vbf[h2 * 2 + 1]);
                    mma_bf16(o_fr[nd], pal, vbf[h2 * 2], vbf[h2 * 2 + 1]);
                    mma_bf16(o_fr[nd], pah, vlf[h2 * 2], vlf[h2 * 2 + 1]);
                }
            }
        }
        __syncthreads();            // PV reads done before next tile's V issue
    }

    // ---- epilogue ----
    const float inv0 = 1.0f / l0;
    const float inv1 = 1.0f / l1;
    const int tr0 = c * WW + half * 128 + w * 16 + (lane >> 2);
    #pragma unroll
    for (int nd = 0; nd < 8; nd++) {
        const int d0 = nd * 8 + (lane & 3) * 2;
        *(float2*)&out[((size_t)b * TT + tr0) * EE + h * SS + d0] =
            make_float2(o_fr[nd][0] * inv0, o_fr[nd][1] * inv0);
        *(float2*)&out[((size_t)b * TT + tr0 + 8) * EE + h * SS + d0] =
            make_float2(o_fr[nd][2] * inv1, o_fr[nd][3] * inv1);
    }
}

// ---------------------------------------------------------------------------
extern "C" void kernel_launch(void* const* d_in, const int* in_sizes, int n_in,
                              void* d_out, int out_size)
{
    const float* x  = (const float*)d_in[0];
    const float* wq = (const float*)d_in[1];
    const float* wk = (const float*)d_in[2];
    const float* wv = (const float*)d_in[3];
    float* out = (float*)d_out;

    cudaFuncSetAttribute(attn_mma_kernel,
                         cudaFuncAttributeMaxDynamicSharedMemorySize, ATT_SMEM);

    convert_kernel<<<(NTOT4 + 255) / 256, 256>>>(x, wq, wk, wv);
    qkv_mma_kernel<<<dim3(NN / 128, EE / 128, 3), 256>>>();
    attn_mma_kernel<<<dim3(2 * CC, BB * HH), 256, ATT_SMEM>>>(out);
}

// round 10
// speedup vs baseline: 1.2206x; 1.2206x over previous
#include <cuda_runtime.h>
#include <cuda_bf16.h>

// Problem constants
#define BB 2
#define TT 4096
#define EE 768
#define HH 12
#define SS 64
#define WW 256
#define CC 16
#define NN (BB * TT)   // 8192

// ---------------------------------------------------------------------------
// Packed split-bf16 scratch (device globals: allocation-free)
// Each uint32 = bf16(hi) in low 16 bits | bf16(residual) in high 16 bits.
// ---------------------------------------------------------------------------
__device__ unsigned g_xp[(size_t)NN * EE];          // x packed          25.2 MB
__device__ unsigned g_wp[(size_t)3 * EE * EE];      // wq|wk|wv packed    7.1 MB
__device__ unsigned g_qp[(size_t)BB * HH * TT * SS];   // [b][h][t][d]
__device__ unsigned g_kp[(size_t)BB * HH * TT * SS];
__device__ unsigned g_vp[(size_t)BB * HH * TT * SS];

// ---------------------------------------------------------------------------
// Helpers
// ---------------------------------------------------------------------------
__device__ __forceinline__ unsigned pack2bf(float lo_elem, float hi_elem) {
    // returns bf16x2 reg: low half = bf16(lo_elem), high half = bf16(hi_elem)
    unsigned r;
    asm("cvt.rn.bf16x2.f32 %0, %1, %2;" : "=r"(r) : "f"(hi_elem), "f"(lo_elem));
    return r;
}
__device__ __forceinline__ unsigned pack_split(float v) {
    float hf = __bfloat162float(__float2bfloat16(v));
    return pack2bf(v, v - hf);   // low = hi-part, high = residual
}
__device__ __forceinline__ unsigned smaddr(const void* p) {
    return (unsigned)__cvta_generic_to_shared(p);
}
__device__ __forceinline__ void ldm_x4(unsigned a, unsigned& r0, unsigned& r1,
                                       unsigned& r2, unsigned& r3) {
    asm volatile("ldmatrix.sync.aligned.m8n8.x4.shared.b16 {%0,%1,%2,%3},[%4];"
                 : "=r"(r0), "=r"(r1), "=r"(r2), "=r"(r3) : "r"(a));
}
__device__ __forceinline__ void ldm_x4t(unsigned a, unsigned& r0, unsigned& r1,
                                        unsigned& r2, unsigned& r3) {
    asm volatile("ldmatrix.sync.aligned.m8n8.x4.trans.shared.b16 {%0,%1,%2,%3},[%4];"
                 : "=r"(r0), "=r"(r1), "=r"(r2), "=r"(r3) : "r"(a));
}
__device__ __forceinline__ void mma_bf16(float* d, const unsigned* a,
                                         unsigned b0, unsigned b1) {
    asm volatile(
        "mma.sync.aligned.m16n8k16.row.col.f32.bf16.bf16.f32 "
        "{%0,%1,%2,%3},{%4,%5,%6,%7},{%8,%9},{%0,%1,%2,%3};"
        : "+f"(d[0]), "+f"(d[1]), "+f"(d[2]), "+f"(d[3])
        : "r"(a[0]), "r"(a[1]), "r"(a[2]), "r"(a[3]), "r"(b0), "r"(b1));
}

// ---------------------------------------------------------------------------
// Pass 0: fp32 -> packed split-bf16 for x and the three weights, one launch.
// ---------------------------------------------------------------------------
#define NX4 (NN * EE / 4)
#define NW4 (EE * EE / 4)
#define NTOT4 (NX4 + 3 * NW4)

__global__ __launch_bounds__(256) void convert_kernel(
    const float* __restrict__ x,  const float* __restrict__ wq,
    const float* __restrict__ wk, const float* __restrict__ wv)
{
    int i = blockIdx.x * 256 + threadIdx.x;
    if (i >= NTOT4) return;
    const float4* src;
    unsigned* dstbase;
    int j;
    if (i < NX4)                  { src = (const float4*)x;  dstbase = g_xp;              j = i; }
    else if (i < NX4 + NW4)       { src = (const float4*)wq; dstbase = g_wp;              j = i - NX4; }
    else if (i < NX4 + 2 * NW4)   { src = (const float4*)wk; dstbase = g_wp + EE * EE;     j = i - NX4 - NW4; }
    else                          { src = (const float4*)wv; dstbase = g_wp + 2 * EE * EE; j = i - NX4 - 2 * NW4; }
    float4 v = src[j];
    uint4 o;
    o.x = pack_split(v.x); o.y = pack_split(v.y);
    o.z = pack_split(v.z); o.w = pack_split(v.w);
    ((uint4*)dstbase)[j] = o;
}

// ---------------------------------------------------------------------------
// Pass 1: Q/K/V = x @ W^T via mma.sync bf16, split accumulation (3 mma).
// 128x128 tile, k-step 16, 256 threads = 8 warps (2x4), warp tile 64x32.
// Epilogue writes packed split-bf16 to g_qp/g_kp/g_vp in [b][h][t][d].
// ---------------------------------------------------------------------------
#define QST 24   // smem row stride (bf16 elems) for 16-wide k tiles

__global__ __launch_bounds__(256) void qkv_mma_kernel()
{
    __shared__ __nv_bfloat16 Ah[128 * QST], Al[128 * QST];
    __shared__ __nv_bfloat16 Bh[128 * QST], Bl[128 * QST];

    const int which = blockIdx.z;
    const unsigned* wp = g_wp + (size_t)which * EE * EE;
    unsigned* dst = (which == 0) ? g_qp : (which == 1) ? g_kp : g_vp;
    const float scale = (which == 0) ? 0.125f : 1.0f;

    const int rowBase = blockIdx.x * 128;
    const int colBase = blockIdx.y * 128;
    const int t    = threadIdx.x;
    const int lane = t & 31;
    const int w    = t >> 5;
    const int wm   = (w >> 2) * 64;
    const int wn   = (w & 3) * 32;

    float acc[4][4][4];
    #pragma unroll
    for (int mt = 0; mt < 4; mt++)
        #pragma unroll
        for (int nt = 0; nt < 4; nt++)
            #pragma unroll
            for (int e = 0; e < 4; e++) acc[mt][nt][e] = 0.0f;

    uint4 pa[2], pb[2];
    // prologue load (k0 = 0)
    #pragma unroll
    for (int j = 0; j < 2; j++) {
        const int s   = t + j * 256;
        const int row = s >> 2;
        const int q4  = (s & 3) * 4;
        pa[j] = *(const uint4*)&g_xp[(size_t)(rowBase + row) * EE + q4];
        pb[j] = *(const uint4*)&wp  [(size_t)(colBase + row) * EE + q4];
    }

    for (int k0 = 0; k0 < EE; k0 += 16) {
        __syncthreads();
        #pragma unroll
        for (int j = 0; j < 2; j++) {
            const int s   = t + j * 256;
            const int row = s >> 2;
            const int q4  = (s & 3) * 4;
            *(unsigned*)&Ah[row * QST + q4]     = __byte_perm(pa[j].x, pa[j].y, 0x5410);
            *(unsigned*)&Ah[row * QST + q4 + 2] = __byte_perm(pa[j].z, pa[j].w, 0x5410);
            *(unsigned*)&Al[row * QST + q4]     = __byte_perm(pa[j].x, pa[j].y, 0x7632);
            *(unsigned*)&Al[row * QST + q4 + 2] = __byte_perm(pa[j].z, pa[j].w, 0x7632);
            *(unsigned*)&Bh[row * QST + q4]     = __byte_perm(pb[j].x, pb[j].y, 0x5410);
            *(unsigned*)&Bh[row * QST + q4 + 2] = __byte_perm(pb[j].z, pb[j].w, 0x5410);
            *(unsigned*)&Bl[row * QST + q4]     = __byte_perm(pb[j].x, pb[j].y, 0x7632);
            *(unsigned*)&Bl[row * QST + q4 + 2] = __byte_perm(pb[j].z, pb[j].w, 0x7632);
        }
        __syncthreads();

        if (k0 + 16 < EE) {
            #pragma unroll
            for (int j = 0; j < 2; j++) {
                const int s   = t + j * 256;
                const int row = s >> 2;
                const int q4  = (s & 3) * 4;
                pa[j] = *(const uint4*)&g_xp[(size_t)(rowBase + row) * EE + k0 + 16 + q4];
                pb[j] = *(const uint4*)&wp  [(size_t)(colBase + row) * EE + k0 + 16 + q4];
            }
        }

        unsigned ah[4][4], al[4][4], bh[2][4], bl[2][4];
        #pragma unroll
        for (int mt = 0; mt < 4; mt++) {
            const int off = (wm + mt * 16 + (lane & 15)) * QST + ((lane >> 4) << 3);
            ldm_x4(smaddr(&Ah[off]), ah[mt][0], ah[mt][1], ah[mt][2], ah[mt][3]);
            ldm_x4(smaddr(&Al[off]), al[mt][0], al[mt][1], al[mt][2], al[mt][3]);
        }
        #pragma unroll
        for (int g = 0; g < 2; g++) {
            const int off = (wn + g * 16 + ((lane >> 4) << 3) + (lane & 7)) * QST
                          + (((lane >> 3) & 1) << 3);
            ldm_x4(smaddr(&Bh[off]), bh[g][0], bh[g][1], bh[g][2], bh[g][3]);
            ldm_x4(smaddr(&Bl[off]), bl[g][0], bl[g][1], bl[g][2], bl[g][3]);
        }
        #pragma unroll
        for (int mt = 0; mt < 4; mt++)
            #pragma unroll
            for (int nt = 0; nt < 4; nt++) {
                const int g  = nt >> 1;
                const int hb = (nt & 1) * 2;
                mma_bf16(acc[mt][nt], ah[mt], bh[g][hb], bh[g][hb + 1]);
                mma_bf16(acc[mt][nt], al[mt], bh[g][hb], bh[g][hb + 1]);
                mma_bf16(acc[mt][nt], ah[mt], bl[g][hb], bl[g][hb + 1]);
            }
    }

    // epilogue: pack split + store [b][h][t][d]
    #pragma unroll
    for (int mt = 0; mt < 4; mt++) {
        const int rg0 = rowBase + wm + mt * 16 + (lane >> 2);
        #pragma unroll
        for (int nt = 0; nt < 4; nt++) {
            const int jc = colBase + wn + nt * 8 + (lane & 3) * 2;
            const int h  = jc >> 6;
            const int d  = jc & 63;
            #pragma unroll
            for (int rh = 0; rh < 2; rh++) {
                const int rg = rg0 + rh * 8;
                const int bb = rg >> 12;
                const int tt = rg & (TT - 1);
                uint2 pv;
                pv.x = pack_split(acc[mt][nt][rh * 2 + 0] * scale);
                pv.y = pack_split(acc[mt][nt][rh * 2 + 1] * scale);
                *(uint2*)&dst[(((size_t)(bb * HH + h) * TT) + tt) * SS + d] = pv;
            }
        }
    }
}

// ---------------------------------------------------------------------------
// Pass 2: fused flash attention, all-mma. Block = 128 q x (b,h); 8 warps,
// warp = 16 q rows x 128 keys per tile. Valid key tiles only; zero-padded
// boundary chunks contribute analytically (r unmasked zero-scores per row,
// V = 0): init m = 0, l = r. Split-bf16.
// ---------------------------------------------------------------------------
#define KST 72                     // smem row stride (bf16) for 64/128-wide tiles
#define ATT_SMEM_ELEMS (4 * 128 * KST)
#define ATT_SMEM_BYTES (ATT_SMEM_ELEMS * 2)

__global__ __launch_bounds__(256) void attn_mma_kernel(float* __restrict__ out)
{
    extern __shared__ __nv_bfloat16 sm[];
    __nv_bfloat16* Kh = sm;
    __nv_bfloat16* Kl = sm + 128 * KST;
    __nv_bfloat16* Vh = sm + 2 * 128 * KST;
    __nv_bfloat16* Vl = sm + 3 * 128 * KST;

    const int c    = blockIdx.x >> 1;
    const int half = blockIdx.x & 1;
    const int bh   = blockIdx.y;
    const int b = bh / HH;
    const int h = bh % HH;

    const int t    = threadIdx.x;
    const int lane = t & 31;
    const int w    = t >> 5;

    // ---- stage Q (128x64) into Kh/Kl, build register-resident Q frags ----
    {
        const unsigned* qb = g_qp + ((size_t)bh * TT + c * WW + half * 128) * SS;
        #pragma unroll
        for (int i = 0; i < 8; i++) {
            const int s   = t + i * 256;
            const int row = s >> 4;
            const int q4  = (s & 15) * 4;
            uint4 v = *(const uint4*)&qb[row * SS + q4];
            *(unsigned*)&Kh[row * KST + q4]     = __byte_perm(v.x, v.y, 0x5410);
            *(unsigned*)&Kh[row * KST + q4 + 2] = __byte_perm(v.z, v.w, 0x5410);
            *(unsigned*)&Kl[row * KST + q4]     = __byte_perm(v.x, v.y, 0x7632);
            *(unsigned*)&Kl[row * KST + q4 + 2] = __byte_perm(v.z, v.w, 0x7632);
        }
    }
    __syncthreads();

    unsigned qh[4][4], ql[4][4];
    #pragma unroll
    for (int kt = 0; kt < 4; kt++) {
        const int off = (w * 16 + (lane & 15)) * KST + kt * 16 + ((lane >> 4) << 3);
        ldm_x4(smaddr(&Kh[off]), qh[kt][0], qh[kt][1], qh[kt][2], qh[kt][3]);
        ldm_x4(smaddr(&Kl[off]), ql[kt][0], ql[kt][1], ql[kt][2], ql[kt][3]);
    }

    float m0 = -1e30f, m1 = -1e30f, l0 = 0.0f, l1 = 0.0f;
    float o_fr[8][4];
    #pragma unroll
    for (int nd = 0; nd < 8; nd++)
        #pragma unroll
        for (int e = 0; e < 4; e++) o_fr[nd][e] = 0.0f;

    const int r0 = half * 128 + w * 16 + (lane >> 2);  // row in chunk, frag row 0
    const int r1 = r0 + 8;

    // ---- analytic boundary-chunk contribution ----
    // c==0:    tiles 0,1 are zero-padded; per row r, exactly r unmasked
    //          zero-scores enter the softmax denominator (V=0).
    // c==CC-1: tiles 4,5; per row r, exactly 255-r unmasked zero-scores.
    if (c == 0) {
        if (r0 > 0) { m0 = 0.0f; l0 = (float)r0; }
        if (r1 > 0) { m1 = 0.0f; l1 = (float)r1; }
    } else if (c == CC - 1) {
        const int a0 = 255 - r0, a1 = 255 - r1;
        if (a0 > 0) { m0 = 0.0f; l0 = (float)a0; }
        if (a1 > 0) { m1 = 0.0f; l1 = (float)a1; }
    }

    const int tstart = (c == 0) ? 2 : 0;
    const int tend   = (c == CC - 1) ? 4 : 6;

    for (int nt = tstart; nt < tend; nt++) {
        const int kc = c - 1 + (nt >> 1);
        const int y0 = (nt & 1) * 128;
        const unsigned* kb = g_kp + ((size_t)bh * TT + kc * WW + y0) * SS;
        const unsigned* vb = g_vp + ((size_t)bh * TT + kc * WW + y0) * SS;

        __syncthreads();   // everyone done with smem from prior tile / Q frags
        #pragma unroll
        for (int i = 0; i < 8; i++) {
            const int s   = t + i * 256;
            const int row = s >> 4;
            const int q4  = (s & 15) * 4;
            uint4 kv = *(const uint4*)&kb[row * SS + q4];
            uint4 vv = *(const uint4*)&vb[row * SS + q4];
            *(unsigned*)&Kh[row * KST + q4]     = __byte_perm(kv.x, kv.y, 0x5410);
            *(unsigned*)&Kh[row * KST + q4 + 2] = __byte_perm(kv.z, kv.w, 0x5410);
            *(unsigned*)&Kl[row * KST + q4]     = __byte_perm(kv.x, kv.y, 0x7632);
            *(unsigned*)&Kl[row * KST + q4 + 2] = __byte_perm(kv.z, kv.w, 0x7632);
            *(unsigned*)&Vh[row * KST + q4]     = __byte_perm(vv.x, vv.y, 0x5410);
            *(unsigned*)&Vh[row * KST + q4 + 2] = __byte_perm(vv.z, vv.w, 0x5410);
            *(unsigned*)&Vl[row * KST + q4]     = __byte_perm(vv.x, vv.y, 0x7632);
            *(unsigned*)&Vl[row * KST + q4 + 2] = __byte_perm(vv.z, vv.w, 0x7632);
        }
        __syncthreads();

        float s_fr[16][4];
        #pragma unroll
        for (int n = 0; n < 16; n++)
            #pragma unroll
            for (int e = 0; e < 4; e++) s_fr[n][e] = 0.0f;

        #pragma unroll
        for (int kt = 0; kt < 4; kt++) {
            #pragma unroll
            for (int g = 0; g < 8; g++) {
                unsigned kbf[4], klf[4];
                const int off = (g * 16 + ((lane >> 4) << 3) + (lane & 7)) * KST
                              + kt * 16 + (((lane >> 3) & 1) << 3);
                ldm_x4(smaddr(&Kh[off]), kbf[0], kbf[1], kbf[2], kbf[3]);
                ldm_x4(smaddr(&Kl[off]), klf[0], klf[1], klf[2], klf[3]);
                #pragma unroll
                for (int h2 = 0; h2 < 2; h2++) {
                    const int n = g * 2 + h2;
                    mma_bf16(s_fr[n], qh[kt], kbf[h2 * 2], kbf[h2 * 2 + 1]);
                    mma_bf16(s_fr[n], ql[kt], kbf[h2 * 2], kbf[h2 * 2 + 1]);
                    mma_bf16(s_fr[n], qh[kt], klf[h2 * 2], klf[h2 * 2 + 1]);
                }
            }
        }

        // ---- online softmax on fragments ----
        float rm0 = -1e30f, rm1 = -1e30f;
        #pragma unroll
        for (int n = 0; n < 16; n++) {
            rm0 = fmaxf(rm0, fmaxf(s_fr[n][0], s_fr[n][1]));
            rm1 = fmaxf(rm1, fmaxf(s_fr[n][2], s_fr[n][3]));
        }
        #pragma unroll
        for (int off = 1; off <= 2; off <<= 1) {
            rm0 = fmaxf(rm0, __shfl_xor_sync(0xFFFFFFFFu, rm0, off));
            rm1 = fmaxf(rm1, __shfl_xor_sync(0xFFFFFFFFu, rm1, off));
        }
        const float mn0 = fmaxf(m0, rm0);
        const float mn1 = fmaxf(m1, rm1);
        const float al0 = __expf(m0 - mn0);
        const float al1 = __expf(m1 - mn1);
        float rs0 = 0.0f, rs1 = 0.0f;
        #pragma unroll
        for (int n = 0; n < 16; n++) {
            s_fr[n][0] = __expf(s_fr[n][0] - mn0);
            s_fr[n][1] = __expf(s_fr[n][1] - mn0);
            s_fr[n][2] = __expf(s_fr[n][2] - mn1);
            s_fr[n][3] = __expf(s_fr[n][3] - mn1);
            rs0 += s_fr[n][0] + s_fr[n][1];
            rs1 += s_fr[n][2] + s_fr[n][3];
        }
        #pragma unroll
        for (int off = 1; off <= 2; off <<= 1) {
            rs0 += __shfl_xor_sync(0xFFFFFFFFu, rs0, off);
            rs1 += __shfl_xor_sync(0xFFFFFFFFu, rs1, off);
        }
        l0 = l0 * al0 + rs0;  m0 = mn0;
        l1 = l1 * al1 + rs1;  m1 = mn1;
        #pragma unroll
        for (int nd = 0; nd < 8; nd++) {
            o_fr[nd][0] *= al0; o_fr[nd][1] *= al0;
            o_fr[nd][2] *= al1; o_fr[nd][3] *= al1;
        }

        // ---- O += P @ V (split P, split V; 3 mma) ----
        #pragma unroll
        for (int ktj = 0; ktj < 8; ktj++) {
            const float* pe = s_fr[2 * ktj];
            const float* po = s_fr[2 * ktj + 1];
            float heA = __bfloat162float(__float2bfloat16(pe[0]));
            float heB = __bfloat162float(__float2bfloat16(pe[1]));
            float heC = __bfloat162float(__float2bfloat16(pe[2]));
            float heD = __bfloat162float(__float2bfloat16(pe[3]));
            float hoA = __bfloat162float(__float2bfloat16(po[0]));
            float hoB = __bfloat162float(__float2bfloat16(po[1]));
            float hoC = __bfloat162float(__float2bfloat16(po[2]));
            float hoD = __bfloat162float(__float2bfloat16(po[3]));
            unsigned pah[4], pal[4];
            pah[0] = pack2bf(pe[0], pe[1]);
            pah[1] = pack2bf(pe[2], pe[3]);
            pah[2] = pack2bf(po[0], po[1]);
            pah[3] = pack2bf(po[2], po[3]);
            pal[0] = pack2bf(pe[0] - heA, pe[1] - heB);
            pal[1] = pack2bf(pe[2] - heC, pe[3] - heD);
            pal[2] = pack2bf(po[0] - hoA, po[1] - hoB);
            pal[3] = pack2bf(po[2] - hoC, po[3] - hoD);

            #pragma unroll
            for (int g = 0; g < 4; g++) {
                unsigned vbf[4], vlf[4];
                const int off = (ktj * 16 + (lane & 15)) * KST
                              + g * 16 + ((lane >> 4) << 3);
                ldm_x4t(smaddr(&Vh[off]), vbf[0], vbf[1], vbf[2], vbf[3]);
                ldm_x4t(smaddr(&Vl[off]), vlf[0], vlf[1], vlf[2], vlf[3]);
                #pragma unroll
                for (int h2 = 0; h2 < 2; h2++) {
                    const int nd = g * 2 + h2;
                    mma_bf16(o_fr[nd], pah, vbf[h2 * 2], vbf[h2 * 2 + 1]);
                    mma_bf16(o_fr[nd], pal, vbf[h2 * 2], vbf[h2 * 2 + 1]);
                    mma_bf16(o_fr[nd], pah, vlf[h2 * 2], vlf[h2 * 2 + 1]);
                }
            }
        }
    }

    // ---- epilogue: normalize + store fp32 ----
    const float inv0 = 1.0f / l0;
    const float inv1 = 1.0f / l1;
    const int tr0 = c * WW + half * 128 + w * 16 + (lane >> 2);
    #pragma unroll
    for (int nd = 0; nd < 8; nd++) {
        const int d0 = nd * 8 + (lane & 3) * 2;
        *(float2*)&out[((size_t)b * TT + tr0) * EE + h * SS + d0] =
            make_float2(o_fr[nd][0] * inv0, o_fr[nd][1] * inv0);
        *(float2*)&out[((size_t)b * TT + tr0 + 8) * EE + h * SS + d0] =
            make_float2(o_fr[nd][2] * inv1, o_fr[nd][3] * inv1);
    }
}

// ---------------------------------------------------------------------------
extern "C" void kernel_launch(void* const* d_in, const int* in_sizes, int n_in,
                              void* d_out, int out_size)
{
    const float* x  = (const float*)d_in[0];
    const float* wq = (const float*)d_in[1];
    const float* wk = (const float*)d_in[2];
    const float* wv = (const float*)d_in[3];
    float* out = (float*)d_out;

    cudaFuncSetAttribute(attn_mma_kernel,
                         cudaFuncAttributeMaxDynamicSharedMemorySize, ATT_SMEM_BYTES);

    convert_kernel<<<(NTOT4 + 255) / 256, 256>>>(x, wq, wk, wv);
    qkv_mma_kernel<<<dim3(NN / 128, EE / 128, 3), 256>>>();
    attn_mma_kernel<<<dim3(2 * CC, BB * HH), 256, ATT_SMEM_BYTES>>>(out);
}